// round 13
// baseline (speedup 1.0000x reference)
#include <cuda_runtime.h>
#include <math.h>
#include <stdint.h>

#define SS   16
#define NG   128
#define NZ   254          // output length along z = 2*(128-1)
#define DIN  3072
#define DH   1024
#define DOUT 49152
#define TWO_PI_F 6.28318530717958647692f

#define MLP2_GRID   148
#define MLP2_SLOT   8192                      // one W2r row (4KB) + one W2i row (4KB)
#define MLP2_SMEM   (8 * 3 * MLP2_SLOT)       // 8 warps x 3-slot ring = 192 KB

// ---------------- scratch (device globals; no allocations) ----------------
__device__ __align__(16) float2 g_Cy[3 * 128 * 16];      // y-DFT of boundary fields
__device__ __align__(16) float  g_xr[DIN];               // MLP input (real)
__device__             float   g_h [DH];                 // hidden layer
__device__ __align__(16) float2 g_o [DOUT];              // complex GEMV output (12,16,16,16)
__device__ __align__(16) float  g_Y1r[12 * 32 * 128 * 16]; // y-transform, real plane
__device__ __align__(16) float  g_Y1i[12 * 32 * 128 * 16]; // y-transform, imag plane

// ---------------- packed f32x2 helpers ----------------
__device__ __forceinline__ unsigned long long fma2(unsigned long long a,
                                                   unsigned long long b,
                                                   unsigned long long c) {
    unsigned long long d;
    asm("fma.rn.f32x2 %0, %1, %2, %3;" : "=l"(d) : "l"(a), "l"(b), "l"(c));
    return d;
}
__device__ __forceinline__ float f2lo(unsigned long long u) {
    return __uint_as_float((unsigned int)u);
}
__device__ __forceinline__ float f2hi(unsigned long long u) {
    return __uint_as_float((unsigned int)(u >> 32));
}
__device__ __forceinline__ unsigned long long pack2(float a, float b) {
    return (unsigned long long)__float_as_uint(a) |
           ((unsigned long long)__float_as_uint(b) << 32);
}

// inline twiddle: e^{+2πi t/128}, t in [0,128)
__device__ __forceinline__ float2 tw128(int t) {
    float s, c;
    sincosf((float)t * (TWO_PI_F / 128.f), &s, &c);
    return make_float2(c, s);
}

// ---------------- mbarrier / bulk-async helpers ----------------
__device__ __forceinline__ uint32_t smem_u32(const void* p) {
    uint32_t a;
    asm("{ .reg .u64 t; cvta.to.shared.u64 t, %1; cvt.u32.u64 %0, t; }"
        : "=r"(a) : "l"(p));
    return a;
}
__device__ __forceinline__ void mbar_init(uint32_t mbar, uint32_t count) {
    asm volatile("mbarrier.init.shared.b64 [%0], %1;" :: "r"(mbar), "r"(count)
                 : "memory");
}
__device__ __forceinline__ void mbar_expect_tx(uint32_t mbar, uint32_t bytes) {
    asm volatile("mbarrier.arrive.expect_tx.shared.b64 _, [%0], %1;"
                 :: "r"(mbar), "r"(bytes) : "memory");
}
__device__ __forceinline__ void mbar_wait(uint32_t mbar, uint32_t phase) {
    asm volatile(
        "{\n\t"
        ".reg .pred P1;\n\t"
        "WAIT_LOOP_%=:\n\t"
        "mbarrier.try_wait.parity.acquire.cta.shared::cta.b64 P1, [%0], %1, 0x989680;\n\t"
        "@P1 bra.uni WAIT_DONE_%=;\n\t"
        "bra.uni WAIT_LOOP_%=;\n\t"
        "WAIT_DONE_%=:\n\t"
        "}"
        :: "r"(mbar), "r"(phase) : "memory");
}
__device__ __forceinline__ void bulk_g2s(uint32_t dst, const void* src,
                                         uint32_t bytes, uint32_t mbar) {
    asm volatile(
        "cp.async.bulk.shared::cta.global.mbarrier::complete_tx::bytes "
        "[%0], [%1], %2, [%3];"
        :: "r"(dst), "l"(src), "r"(bytes), "r"(mbar) : "memory");
}
__device__ __forceinline__ void fence_proxy_async_shared() {
    asm volatile("fence.proxy.async.shared::cta;" ::: "memory");
}

// ---------------- K1a: forward DFT along y (16 modes) ----------------
__global__ void k_dft_y(const float* __restrict__ Br, const float* __restrict__ Bp,
                        const float* __restrict__ Bt) {
    int f = blockIdx.x >> 7;
    int x = blockIdx.x & 127;
    const float* src = (f == 0) ? Bp : (f == 1) ? Bt : Br;
    float sgn = (f == 1) ? -1.f : 1.f;
    __shared__ float  row[128];
    __shared__ float2 tw[128];
    int t = threadIdx.x;
    row[t] = sgn * src[x * 128 + t];
    tw[t]  = tw128(t);
    __syncthreads();
    if (t < 16) {
        float re = 0.f, im = 0.f;
        #pragma unroll 8
        for (int y = 0; y < 128; y++) {
            float2 w = tw[(t * y) & 127];
            float v = row[y];
            re += v * w.x;
            im -= v * w.y;
        }
        g_Cy[(f * 128 + x) * 16 + t] = make_float2(re, im);
    }
}

// ---------------- K1b: forward DFT along x (32 modes) -> xr --------------
__global__ __launch_bounds__(256) void k_dft_x() {
    int b = blockIdx.x;           // 0..95  (f*32 + kxi)
    int f = b / 32, kxi = b % 32;
    __shared__ float2 tw[128];
    __shared__ float2 red[256];
    int t = threadIdx.x;
    if (t < 128) tw[t] = tw128(t);
    __syncthreads();
    int ky = t & 15, xc = t >> 4;           // xc: 0..15, 8 x's each
    int kxe = (kxi < 16) ? kxi : (kxi + 96);
    float re = 0.f, im = 0.f;
    #pragma unroll
    for (int j = 0; j < 8; j++) {
        int x = xc * 8 + j;
        float2 c = g_Cy[(f * 128 + x) * 16 + ky];
        float2 w = tw[(kxe * x) & 127];
        re += c.x * w.x + c.y * w.y;
        im += c.y * w.x - c.x * w.y;
    }
    red[t] = make_float2(re, im);
    __syncthreads();
    #pragma unroll
    for (int s = 8; s >= 1; s >>= 1) {
        if (xc < s) {
            red[t].x += red[t + 16 * s].x;
            red[t].y += red[t + 16 * s].y;
        }
        __syncthreads();
    }
    if (t < 16) {
        int seg = f * 512 + (kxi >= 16 ? 256 : 0) + (kxi & 15) * 16 + t;
        g_xr[seg]        = red[t].x;
        g_xr[1536 + seg] = red[t].y;
    }
}

// ---------------- K2: hidden GEMV + sigmoid (no staging, direct L2) ------
__global__ __launch_bounds__(256) void k_mlp1(const float* __restrict__ W1,
                                              const float* __restrict__ b1) {
    __shared__ float part[8];
    int t = threadIdx.x;
    int w = t >> 5, lane = t & 31;
    int row = blockIdx.x * 2 + (w >> 2);    // 2 rows per block
    int q   = w & 3;                        // quarter of the row
    const float4* wr = (const float4*)(W1 + (size_t)row * DIN) + q * 192;
    const float4* xv = ((const float4*)g_xr) + q * 192;
    float acc = 0.f;
    #pragma unroll
    for (int k = 0; k < 6; k++) {
        int j = lane + 32 * k;
        float4 a = wr[j];
        float4 x4 = __ldg(xv + j);
        acc += a.x * x4.x + a.y * x4.y + a.z * x4.z + a.w * x4.w;
    }
    #pragma unroll
    for (int o = 16; o > 0; o >>= 1)
        acc += __shfl_xor_sync(0xffffffffu, acc, o);
    if (lane == 0) part[w] = acc;
    __syncthreads();
    if (t < 2) {
        int r2 = blockIdx.x * 2 + t;
        float v = part[t * 4] + part[t * 4 + 1] + part[t * 4 + 2] + part[t * 4 + 3]
                + b1[r2];
        g_h[r2] = 1.f / (1.f + expf(-v));
    }
}

// ---------------- K3: complex GEMV — per-warp TMA ring, ONE launch -------
// 148 persistent CTAs x 8 warps, grid-strided over all rows. Each warp owns
// a 3-slot ring (slot = W2r row + W2i row = 8 KB) with its own mbarrier;
// refills issue right after a slot is consumed. Nothing else runs
// concurrently -> pure-read stream (tests the mixed-traffic-ceiling theory).
__global__ __launch_bounds__(256) void k_mlp2(int row0, int nrows,
                                              const float* __restrict__ W2r,
                                              const float* __restrict__ W2i,
                                              const float* __restrict__ b2r,
                                              const float* __restrict__ b2i) {
    extern __shared__ __align__(16) unsigned char sbuf[];   // 8*3*8192
    __shared__ __align__(16) float sh[DH];
    __shared__ __align__(8) unsigned long long mbars[24];
    int t = threadIdx.x;
    for (int i = t; i < DH; i += 256) sh[i] = g_h[i];
    if (t < 24) mbar_init(smem_u32(&mbars[t]), 1);
    fence_proxy_async_shared();
    __syncthreads();

    int w = t >> 5, lane = t & 31;
    const int stride = MLP2_GRID * 8;               // 1184 warps total
    int wg = blockIdx.x * 8 + w;
    int nIter = (nrows - wg + stride - 1) / stride;

    uint32_t slot0 = smem_u32(sbuf) + (uint32_t)(w * 3) * MLP2_SLOT;
    uint32_t mb0   = smem_u32(&mbars[w * 3]);

    // prologue: fill up to 3 slots
    if (lane == 0) {
        int pre = nIter < 3 ? nIter : 3;
        for (int s = 0; s < pre; s++) {
            size_t row = (size_t)row0 + wg + (size_t)s * stride;
            uint32_t mb = mb0 + s * 8;
            mbar_expect_tx(mb, MLP2_SLOT);
            bulk_g2s(slot0 + s * MLP2_SLOT,        W2r + row * DH, 4096, mb);
            bulk_g2s(slot0 + s * MLP2_SLOT + 4096, W2i + row * DH, 4096, mb);
        }
    }

    const float4* hv = (const float4*)sh;
    unsigned int phbits = 0;
    int s = 0;
    for (int i = 0; i < nIter; i++) {
        uint32_t mb = mb0 + s * 8;
        mbar_wait(mb, (phbits >> s) & 1u);
        phbits ^= 1u << s;

        const float4* r4 = (const float4*)(sbuf + (w * 3 + s) * MLP2_SLOT);
        const float4* i4 = r4 + 256;
        float ar = 0.f, ai = 0.f;
        #pragma unroll
        for (int k = 0; k < 8; k++) {
            int j = lane + 32 * k;
            float4 h4 = hv[j];
            float4 a = r4[j];
            float4 b = i4[j];
            ar += a.x * h4.x + a.y * h4.y + a.z * h4.z + a.w * h4.w;
            ai += b.x * h4.x + b.y * h4.y + b.z * h4.z + b.w * h4.w;
        }
        #pragma unroll
        for (int o = 16; o > 0; o >>= 1) {
            ar += __shfl_xor_sync(0xffffffffu, ar, o);
            ai += __shfl_xor_sync(0xffffffffu, ai, o);
        }
        int row = row0 + wg + i * stride;
        if (lane == 0) g_o[row] = make_float2(ar + b2r[row], ai + b2i[row]);

        __syncwarp();
        if (i + 3 < nIter && lane == 0) {      // refill this slot
            size_t nrow = (size_t)row + (size_t)3 * stride;
            mbar_expect_tx(mb, MLP2_SLOT);
            bulk_g2s(slot0 + s * MLP2_SLOT,        W2r + nrow * DH, 4096, mb);
            bulk_g2s(slot0 + s * MLP2_SLOT + 4096, W2i + nrow * DH, 4096, mb);
        }
        s = (s == 2) ? 0 : s + 1;
    }
}

// ---------------- K4: inverse DFT along y (all fields) -------------------
__global__ void k_stage_y() {
    int kxi = blockIdx.x;   // 0..31
    int f   = blockIdx.y;   // 0..2
    int yt  = blockIdx.z;   // 0..3
    __shared__ float2 Bsh[512];
    __shared__ float2 tw[128];
    int t = threadIdx.x;
    if (t < 128) tw[t] = tw128(t);
    int hx = (kxi >= 16) ? 1 : 0, p = kxi & 15;
    for (int e = t; e < 512; e += 256) {
        int kyi = e >> 4, kz = e & 15;
        int blk = f * 4 + hx * 2 + (kyi >= 16 ? 1 : 0);
        Bsh[e] = g_o[blk * 4096 + p * 256 + (kyi & 15) * 16 + kz];
    }
    __syncthreads();
    float mx = (kxi < 16) ? (float)kxi : (float)(kxi - 32);
    for (int it = t; it < 512; it += 256) {
        int y  = yt * 32 + (it >> 4);
        int kz = it & 15;
        float Sr = 0.f, Si = 0.f, Tr = 0.f, Ti = 0.f;
        #pragma unroll
        for (int kyi = 0; kyi < 32; kyi++) {
            int   kye = (kyi < 16) ? kyi : (kyi + 96);
            float my  = (kyi < 16) ? (float)kyi : (float)(kyi - 32);
            float2 w = tw[(kye * y) & 127];
            float2 B = Bsh[kyi * 16 + kz];
            Sr += B.x * w.x - B.y * w.y;
            Si += B.x * w.y + B.y * w.x;
            float br = -my * B.y, bi = my * B.x;   // i*my*B
            Tr += br * w.x - bi * w.y;
            Ti += br * w.y + bi * w.x;
        }
        int rest = (kxi * 128 + y) * 16 + kz;
        float fz = (float)kz;
        g_Y1r[ f          * 65536 + rest] = Sr;
        g_Y1i[ f          * 65536 + rest] = Si;
        g_Y1r[(3 + 3 * f) * 65536 + rest] = -mx * Si;
        g_Y1i[(3 + 3 * f) * 65536 + rest] =  mx * Sr;
        g_Y1r[(4 + 3 * f) * 65536 + rest] = Tr;
        g_Y1i[(4 + 3 * f) * 65536 + rest] = Ti;
        g_Y1r[(5 + 3 * f) * 65536 + rest] = -fz * Si;
        g_Y1i[(5 + 3 * f) * 65536 + rest] =  fz * Sr;
    }
}

// ---------------- K5: FUSED x-DFT + z-transform (all 12 channels) --------
__global__ __launch_bounds__(256) void k_stage_xz(float* __restrict__ out) {
    int y = blockIdx.x;                 // 0..127
    int c = blockIdx.y;                 // 0..11
    __shared__ __align__(16) float Yr[512];
    __shared__ __align__(16) float Yi[512];
    __shared__ __align__(16) float Frs[2048];   // [x][16 kz]
    __shared__ __align__(16) float Fis[2048];
    __shared__ float2 tw[128];
    int t = threadIdx.x;
    if (t < 128) tw[t] = tw128(t);
    for (int e = t; e < 512; e += 256) {
        int idx = c * 65536 + ((e >> 4) * 128 + y) * 16 + (e & 15);
        Yr[e] = g_Y1r[idx];
        Yi[e] = g_Y1i[idx];
    }
    __syncthreads();

    // Phase 1: x-DFT (packed f32x2 over kz pairs)
    const unsigned long long* Yr2 = (const unsigned long long*)Yr; // [kxi*8+kzp]
    const unsigned long long* Yi2 = (const unsigned long long*)Yi;
    unsigned long long* Fr2w = (unsigned long long*)Frs;           // [x*8+kzp]
    unsigned long long* Fi2w = (unsigned long long*)Fis;
    #pragma unroll
    for (int rep = 0; rep < 4; rep++) {
        int it = t + rep * 256;
        int x = it >> 3, kzp = it & 7;
        unsigned long long r01 = 0ull, i01 = 0ull;
        #pragma unroll
        for (int kxi = 0; kxi < 32; kxi++) {
            int kxe = (kxi < 16) ? kxi : (kxi + 96);
            float2 w = tw[(kxe * x) & 127];
            unsigned long long wx2 = pack2(w.x,  w.x);
            unsigned long long wy2 = pack2(w.y,  w.y);
            unsigned long long wyn = pack2(-w.y, -w.y);
            unsigned long long vr = Yr2[kxi * 8 + kzp];
            unsigned long long vi = Yi2[kxi * 8 + kzp];
            r01 = fma2(vr, wx2, r01);
            r01 = fma2(vi, wyn, r01);
            i01 = fma2(vr, wy2, i01);
            i01 = fma2(vi, wx2, i01);
        }
        Fr2w[x * 8 + kzp] = r01;
        Fi2w[x * 8 + kzp] = i01;
    }
    __syncthreads();

    // Phase 2: z-transform with symmetry; twiddles inline (mod-reduced args)
    int zp = t & 127, half = t >> 7;
    unsigned long long C[8], Sn[8];
    const float n3inv = 1.f / ((float)NG * (float)NG * (float)NZ);
    #pragma unroll
    for (int k = 0; k < 8; k++) {
        int m0 = (2 * k * zp) % NZ;
        int m1 = ((2 * k + 1) * zp) % NZ;
        float s0, c0, s1, c1;
        sincosf((float)m0 * (TWO_PI_F / (float)NZ), &s0, &c0);
        sincosf((float)m1 * (TWO_PI_F / (float)NZ), &s1, &c1);
        float w0 = (k == 0 ? 1.f : 2.f) * n3inv;
        float w1 = 2.f * n3inv;
        C [k] = pack2(w0 * c0, w1 * c1);
        Sn[k] = pack2(w0 * s0, w1 * s1);
    }
    const ulonglong2* Fr2 = (const ulonglong2*)Frs;  // [x*4 + q]
    const ulonglong2* Fi2 = (const ulonglong2*)Fis;
    float* obase = out + ((size_t)c * 128 * 128 + y) * NZ;
    for (int x = half; x < 128; x += 2) {
        unsigned long long a = 0ull, b = 0ull;
        #pragma unroll
        for (int q = 0; q < 4; q++) {
            ulonglong2 vr = Fr2[x * 4 + q];
            ulonglong2 vi = Fi2[x * 4 + q];
            a = fma2(vr.x, C [2 * q],     a);
            a = fma2(vr.y, C [2 * q + 1], a);
            b = fma2(vi.x, Sn[2 * q],     b);
            b = fma2(vi.y, Sn[2 * q + 1], b);
        }
        float A = f2lo(a) + f2hi(a);
        float B = f2lo(b) + f2hi(b);
        float* orow = obase + (size_t)x * (128 * NZ);
        orow[zp] = A - B;
        if (zp >= 1 && zp < 127) orow[254 - zp] = A + B;
    }
}

// ---------------- launch ----------------
extern "C" void kernel_launch(void* const* d_in, const int* in_sizes, int n_in,
                              void* d_out, int out_size) {
    const float* Br  = (const float*)d_in[0];
    const float* Bp  = (const float*)d_in[1];
    const float* Bt  = (const float*)d_in[2];
    const float* W1  = (const float*)d_in[3];
    const float* b1  = (const float*)d_in[4];
    const float* W2r = (const float*)d_in[5];
    const float* W2i = (const float*)d_in[6];
    const float* b2r = (const float*)d_in[7];
    const float* b2i = (const float*)d_in[8];
    float* out = (float*)d_out;

    static int inited = 0;
    if (!inited) {
        cudaFuncSetAttribute(k_mlp2, cudaFuncAttributeMaxDynamicSharedMemorySize,
                             MLP2_SMEM);
        inited = 1;
    }

    // fully serial, single stream — mlp2 runs as a pure-read phase
    k_dft_y  <<<384, 128>>>(Br, Bp, Bt);
    k_dft_x  <<<96, 256>>>();
    k_mlp1   <<<512, 256>>>(W1, b1);
    k_mlp2   <<<MLP2_GRID, 256, MLP2_SMEM>>>(0, DOUT, W2r, W2i, b2r, b2i);
    k_stage_y<<<dim3(32, 3, 4), 256>>>();
    k_stage_xz<<<dim3(128, 12), 256>>>(out);
}

// round 14
// speedup vs baseline: 1.0643x; 1.0643x over previous
#include <cuda_runtime.h>
#include <math.h>
#include <stdint.h>

#define SS   16
#define NG   128
#define NZ   254          // output length along z = 2*(128-1)
#define DIN  3072
#define DH   1024
#define DOUT 49152
#define PI_D 3.14159265358979323846

#define MLP2_GRID   148
#define MLP2_SLOT   8192                      // one W2r row (4KB) + one W2i row (4KB)
#define MLP2_SMEM   (8 * 3 * MLP2_SLOT)       // 8 warps x 3-slot ring = 192 KB

// ---------------- scratch (device globals; no allocations) ----------------
__device__ __align__(16) float2 g_Cy[3 * 128 * 16];      // y-DFT of boundary fields
__device__ __align__(16) float  g_xr[DIN];               // MLP input (real)
__device__             float   g_h [DH];                 // hidden layer
__device__ __align__(16) float2 g_o [DOUT];              // complex GEMV output (12,16,16,16)
__device__ __align__(16) float  g_Y1r[12 * 32 * 128 * 16]; // y-transform, real plane
__device__ __align__(16) float  g_Y1i[12 * 32 * 128 * 16]; // y-transform, imag plane
__device__             float2  g_tw128[128];             // e^{+2πi t/128}
__device__ __align__(16) float2 g_twc[8 * 128];          // (w cos) pairs: [k][zp] -> kz=2k,2k+1
__device__ __align__(16) float2 g_tws[8 * 128];          // (w sin) pairs

// ---------------- packed f32x2 helpers ----------------
__device__ __forceinline__ unsigned long long fma2(unsigned long long a,
                                                   unsigned long long b,
                                                   unsigned long long c) {
    unsigned long long d;
    asm("fma.rn.f32x2 %0, %1, %2, %3;" : "=l"(d) : "l"(a), "l"(b), "l"(c));
    return d;
}
__device__ __forceinline__ float f2lo(unsigned long long u) {
    return __uint_as_float((unsigned int)u);
}
__device__ __forceinline__ float f2hi(unsigned long long u) {
    return __uint_as_float((unsigned int)(u >> 32));
}
__device__ __forceinline__ unsigned long long pack2(float a, float b) {
    return (unsigned long long)__float_as_uint(a) |
           ((unsigned long long)__float_as_uint(b) << 32);
}

// ---------------- mbarrier / bulk-async helpers ----------------
__device__ __forceinline__ uint32_t smem_u32(const void* p) {
    uint32_t a;
    asm("{ .reg .u64 t; cvta.to.shared.u64 t, %1; cvt.u32.u64 %0, t; }"
        : "=r"(a) : "l"(p));
    return a;
}
__device__ __forceinline__ void mbar_init(uint32_t mbar, uint32_t count) {
    asm volatile("mbarrier.init.shared.b64 [%0], %1;" :: "r"(mbar), "r"(count)
                 : "memory");
}
__device__ __forceinline__ void mbar_expect_tx(uint32_t mbar, uint32_t bytes) {
    asm volatile("mbarrier.arrive.expect_tx.shared.b64 _, [%0], %1;"
                 :: "r"(mbar), "r"(bytes) : "memory");
}
__device__ __forceinline__ void mbar_wait(uint32_t mbar, uint32_t phase) {
    asm volatile(
        "{\n\t"
        ".reg .pred P1;\n\t"
        "WAIT_LOOP_%=:\n\t"
        "mbarrier.try_wait.parity.acquire.cta.shared::cta.b64 P1, [%0], %1, 0x989680;\n\t"
        "@P1 bra.uni WAIT_DONE_%=;\n\t"
        "bra.uni WAIT_LOOP_%=;\n\t"
        "WAIT_DONE_%=:\n\t"
        "}"
        :: "r"(mbar), "r"(phase) : "memory");
}
__device__ __forceinline__ void bulk_g2s(uint32_t dst, const void* src,
                                         uint32_t bytes, uint32_t mbar) {
    asm volatile(
        "cp.async.bulk.shared::cta.global.mbarrier::complete_tx::bytes "
        "[%0], [%1], %2, [%3];"
        :: "r"(dst), "l"(src), "r"(bytes), "r"(mbar) : "memory");
}
__device__ __forceinline__ void fence_proxy_async_shared() {
    asm volatile("fence.proxy.async.shared::cta;" ::: "memory");
}

// ---------------- K0: twiddle tables (double precision, deterministic) ----
__global__ void k_init_tw() {
    int i = blockIdx.x * blockDim.x + threadIdx.x;
    if (i < 128) {
        double a = 2.0 * PI_D * (double)i / 128.0;
        g_tw128[i] = make_float2((float)cos(a), (float)sin(a));
    }
    if (i < 8 * 128) {
        int k = i >> 7, zp = i & 127;
        double n3 = (double)NG * (double)NG * (double)NZ;
        int kz0 = 2 * k, kz1 = 2 * k + 1;
        double w0 = (kz0 == 0 ? 1.0 : 2.0) / n3;
        double w1 = 2.0 / n3;
        double a0 = 2.0 * PI_D * (double)(kz0 * zp) / (double)NZ;
        double a1 = 2.0 * PI_D * (double)(kz1 * zp) / (double)NZ;
        g_twc[i] = make_float2((float)(w0 * cos(a0)), (float)(w1 * cos(a1)));
        g_tws[i] = make_float2((float)(w0 * sin(a0)), (float)(w1 * sin(a1)));
    }
}

// ---------------- K1a: forward DFT along y (16 modes) ----------------
__global__ void k_dft_y(const float* __restrict__ Br, const float* __restrict__ Bp,
                        const float* __restrict__ Bt) {
    int f = blockIdx.x >> 7;
    int x = blockIdx.x & 127;
    const float* src = (f == 0) ? Bp : (f == 1) ? Bt : Br;
    float sgn = (f == 1) ? -1.f : 1.f;
    __shared__ float  row[128];
    __shared__ float2 tw[128];
    int t = threadIdx.x;
    row[t] = sgn * src[x * 128 + t];
    tw[t]  = g_tw128[t];
    __syncthreads();
    if (t < 16) {
        float re = 0.f, im = 0.f;
        #pragma unroll 8
        for (int y = 0; y < 128; y++) {
            float2 w = tw[(t * y) & 127];
            float v = row[y];
            re += v * w.x;
            im -= v * w.y;
        }
        g_Cy[(f * 128 + x) * 16 + t] = make_float2(re, im);
    }
}

// ---------------- K1b: forward DFT along x (32 modes) -> xr --------------
__global__ __launch_bounds__(256) void k_dft_x() {
    int b = blockIdx.x;           // 0..95  (f*32 + kxi)
    int f = b / 32, kxi = b % 32;
    __shared__ float2 tw[128];
    __shared__ float2 red[256];
    int t = threadIdx.x;
    if (t < 128) tw[t] = g_tw128[t];
    __syncthreads();
    int ky = t & 15, xc = t >> 4;           // xc: 0..15, 8 x's each
    int kxe = (kxi < 16) ? kxi : (kxi + 96);
    float re = 0.f, im = 0.f;
    #pragma unroll
    for (int j = 0; j < 8; j++) {
        int x = xc * 8 + j;
        float2 c = g_Cy[(f * 128 + x) * 16 + ky];
        float2 w = tw[(kxe * x) & 127];
        re += c.x * w.x + c.y * w.y;
        im += c.y * w.x - c.x * w.y;
    }
    red[t] = make_float2(re, im);
    __syncthreads();
    #pragma unroll
    for (int s = 8; s >= 1; s >>= 1) {
        if (xc < s) {
            red[t].x += red[t + 16 * s].x;
            red[t].y += red[t + 16 * s].y;
        }
        __syncthreads();
    }
    if (t < 16) {
        int seg = f * 512 + (kxi >= 16 ? 256 : 0) + (kxi & 15) * 16 + t;
        g_xr[seg]        = red[t].x;
        g_xr[1536 + seg] = red[t].y;
    }
}

// ---------------- K2: hidden GEMV + sigmoid (no staging, direct L2) ------
__global__ __launch_bounds__(256) void k_mlp1(const float* __restrict__ W1,
                                              const float* __restrict__ b1) {
    __shared__ float part[8];
    int t = threadIdx.x;
    int w = t >> 5, lane = t & 31;
    int row = blockIdx.x * 2 + (w >> 2);    // 2 rows per block
    int q   = w & 3;                        // quarter of the row
    const float4* wr = (const float4*)(W1 + (size_t)row * DIN) + q * 192;
    const float4* xv = ((const float4*)g_xr) + q * 192;
    float acc = 0.f;
    #pragma unroll
    for (int k = 0; k < 6; k++) {
        int j = lane + 32 * k;
        float4 a = wr[j];
        float4 x4 = __ldg(xv + j);
        acc += a.x * x4.x + a.y * x4.y + a.z * x4.z + a.w * x4.w;
    }
    #pragma unroll
    for (int o = 16; o > 0; o >>= 1)
        acc += __shfl_xor_sync(0xffffffffu, acc, o);
    if (lane == 0) part[w] = acc;
    __syncthreads();
    if (t < 2) {
        int r2 = blockIdx.x * 2 + t;
        float v = part[t * 4] + part[t * 4 + 1] + part[t * 4 + 2] + part[t * 4 + 3]
                + b1[r2];
        g_h[r2] = 1.f / (1.f + expf(-v));
    }
}

// ---------------- K3: complex GEMV — per-warp TMA ring, ONE launch -------
// 148 persistent CTAs x 8 warps, grid-strided over all rows. Each warp owns
// a 3-slot ring (slot = W2r row + W2i row = 8 KB) with its own mbarrier;
// refills issue right after a slot is consumed. Runs serial (nothing
// concurrent) -> pure-read stream at ~5.3 TB/s (measured R13).
__global__ __launch_bounds__(256) void k_mlp2(int row0, int nrows,
                                              const float* __restrict__ W2r,
                                              const float* __restrict__ W2i,
                                              const float* __restrict__ b2r,
                                              const float* __restrict__ b2i) {
    extern __shared__ __align__(16) unsigned char sbuf[];   // 8*3*8192
    __shared__ __align__(16) float sh[DH];
    __shared__ __align__(8) unsigned long long mbars[24];
    int t = threadIdx.x;
    for (int i = t; i < DH; i += 256) sh[i] = g_h[i];
    if (t < 24) mbar_init(smem_u32(&mbars[t]), 1);
    fence_proxy_async_shared();
    __syncthreads();

    int w = t >> 5, lane = t & 31;
    const int stride = MLP2_GRID * 8;               // 1184 warps total
    int wg = blockIdx.x * 8 + w;
    int nIter = (nrows - wg + stride - 1) / stride;

    uint32_t slot0 = smem_u32(sbuf) + (uint32_t)(w * 3) * MLP2_SLOT;
    uint32_t mb0   = smem_u32(&mbars[w * 3]);

    // prologue: fill up to 3 slots
    if (lane == 0) {
        int pre = nIter < 3 ? nIter : 3;
        for (int s = 0; s < pre; s++) {
            size_t row = (size_t)row0 + wg + (size_t)s * stride;
            uint32_t mb = mb0 + s * 8;
            mbar_expect_tx(mb, MLP2_SLOT);
            bulk_g2s(slot0 + s * MLP2_SLOT,        W2r + row * DH, 4096, mb);
            bulk_g2s(slot0 + s * MLP2_SLOT + 4096, W2i + row * DH, 4096, mb);
        }
    }

    const float4* hv = (const float4*)sh;
    unsigned int phbits = 0;
    int s = 0;
    for (int i = 0; i < nIter; i++) {
        uint32_t mb = mb0 + s * 8;
        mbar_wait(mb, (phbits >> s) & 1u);
        phbits ^= 1u << s;

        const float4* r4 = (const float4*)(sbuf + (w * 3 + s) * MLP2_SLOT);
        const float4* i4 = r4 + 256;
        float ar = 0.f, ai = 0.f;
        #pragma unroll
        for (int k = 0; k < 8; k++) {
            int j = lane + 32 * k;
            float4 h4 = hv[j];
            float4 a = r4[j];
            float4 b = i4[j];
            ar += a.x * h4.x + a.y * h4.y + a.z * h4.z + a.w * h4.w;
            ai += b.x * h4.x + b.y * h4.y + b.z * h4.z + b.w * h4.w;
        }
        #pragma unroll
        for (int o = 16; o > 0; o >>= 1) {
            ar += __shfl_xor_sync(0xffffffffu, ar, o);
            ai += __shfl_xor_sync(0xffffffffu, ai, o);
        }
        int row = row0 + wg + i * stride;
        if (lane == 0) g_o[row] = make_float2(ar + b2r[row], ai + b2i[row]);

        __syncwarp();
        if (i + 3 < nIter && lane == 0) {      // refill this slot
            size_t nrow = (size_t)row + (size_t)3 * stride;
            mbar_expect_tx(mb, MLP2_SLOT);
            bulk_g2s(slot0 + s * MLP2_SLOT,        W2r + nrow * DH, 4096, mb);
            bulk_g2s(slot0 + s * MLP2_SLOT + 4096, W2i + nrow * DH, 4096, mb);
        }
        s = (s == 2) ? 0 : s + 1;
    }
}

// ---------------- K4: inverse DFT along y (all fields) -------------------
__global__ void k_stage_y() {
    int kxi = blockIdx.x;   // 0..31
    int f   = blockIdx.y;   // 0..2
    int yt  = blockIdx.z;   // 0..3
    __shared__ float2 Bsh[512];
    __shared__ float2 tw[128];
    int t = threadIdx.x;
    if (t < 128) tw[t] = g_tw128[t];
    int hx = (kxi >= 16) ? 1 : 0, p = kxi & 15;
    for (int e = t; e < 512; e += 256) {
        int kyi = e >> 4, kz = e & 15;
        int blk = f * 4 + hx * 2 + (kyi >= 16 ? 1 : 0);
        Bsh[e] = g_o[blk * 4096 + p * 256 + (kyi & 15) * 16 + kz];
    }
    __syncthreads();
    float mx = (kxi < 16) ? (float)kxi : (float)(kxi - 32);
    for (int it = t; it < 512; it += 256) {
        int y  = yt * 32 + (it >> 4);
        int kz = it & 15;
        float Sr = 0.f, Si = 0.f, Tr = 0.f, Ti = 0.f;
        #pragma unroll
        for (int kyi = 0; kyi < 32; kyi++) {
            int   kye = (kyi < 16) ? kyi : (kyi + 96);
            float my  = (kyi < 16) ? (float)kyi : (float)(kyi - 32);
            float2 w = tw[(kye * y) & 127];
            float2 B = Bsh[kyi * 16 + kz];
            Sr += B.x * w.x - B.y * w.y;
            Si += B.x * w.y + B.y * w.x;
            float br = -my * B.y, bi = my * B.x;   // i*my*B
            Tr += br * w.x - bi * w.y;
            Ti += br * w.y + bi * w.x;
        }
        int rest = (kxi * 128 + y) * 16 + kz;
        float fz = (float)kz;
        g_Y1r[ f          * 65536 + rest] = Sr;
        g_Y1i[ f          * 65536 + rest] = Si;
        g_Y1r[(3 + 3 * f) * 65536 + rest] = -mx * Si;
        g_Y1i[(3 + 3 * f) * 65536 + rest] =  mx * Sr;
        g_Y1r[(4 + 3 * f) * 65536 + rest] = Tr;
        g_Y1i[(4 + 3 * f) * 65536 + rest] = Ti;
        g_Y1r[(5 + 3 * f) * 65536 + rest] = -fz * Si;
        g_Y1i[(5 + 3 * f) * 65536 + rest] =  fz * Sr;
    }
}

// ---------------- K5: FUSED x-DFT + z-transform (all 12 channels) --------
__global__ __launch_bounds__(256) void k_stage_xz(float* __restrict__ out) {
    int y = blockIdx.x;                 // 0..127
    int c = blockIdx.y;                 // 0..11
    __shared__ __align__(16) float Yr[512];
    __shared__ __align__(16) float Yi[512];
    __shared__ __align__(16) float Frs[2048];   // [x][16 kz]
    __shared__ __align__(16) float Fis[2048];
    __shared__ float2 tw[128];
    int t = threadIdx.x;
    if (t < 128) tw[t] = g_tw128[t];
    for (int e = t; e < 512; e += 256) {
        int idx = c * 65536 + ((e >> 4) * 128 + y) * 16 + (e & 15);
        Yr[e] = g_Y1r[idx];
        Yi[e] = g_Y1i[idx];
    }
    __syncthreads();

    // Phase 1: x-DFT (packed f32x2 over kz pairs)
    const unsigned long long* Yr2 = (const unsigned long long*)Yr; // [kxi*8+kzp]
    const unsigned long long* Yi2 = (const unsigned long long*)Yi;
    unsigned long long* Fr2w = (unsigned long long*)Frs;           // [x*8+kzp]
    unsigned long long* Fi2w = (unsigned long long*)Fis;
    #pragma unroll
    for (int rep = 0; rep < 4; rep++) {
        int it = t + rep * 256;
        int x = it >> 3, kzp = it & 7;
        unsigned long long r01 = 0ull, i01 = 0ull;
        #pragma unroll
        for (int kxi = 0; kxi < 32; kxi++) {
            int kxe = (kxi < 16) ? kxi : (kxi + 96);
            float2 w = tw[(kxe * x) & 127];
            unsigned long long wx2 = pack2(w.x,  w.x);
            unsigned long long wy2 = pack2(w.y,  w.y);
            unsigned long long wyn = pack2(-w.y, -w.y);
            unsigned long long vr = Yr2[kxi * 8 + kzp];
            unsigned long long vi = Yi2[kxi * 8 + kzp];
            r01 = fma2(vr, wx2, r01);
            r01 = fma2(vi, wyn, r01);
            i01 = fma2(vr, wy2, i01);
            i01 = fma2(vi, wx2, i01);
        }
        Fr2w[x * 8 + kzp] = r01;
        Fi2w[x * 8 + kzp] = i01;
    }
    __syncthreads();

    // Phase 2: z-transform with symmetry (table twiddles)
    int zp = t & 127, half = t >> 7;
    unsigned long long C[8], Sn[8];
    #pragma unroll
    for (int k = 0; k < 8; k++) {
        float2 cc = g_twc[k * 128 + zp];
        float2 ss = g_tws[k * 128 + zp];
        C [k] = pack2(cc.x, cc.y);
        Sn[k] = pack2(ss.x, ss.y);
    }
    const ulonglong2* Fr2 = (const ulonglong2*)Frs;  // [x*4 + q]
    const ulonglong2* Fi2 = (const ulonglong2*)Fis;
    float* obase = out + ((size_t)c * 128 * 128 + y) * NZ;
    for (int x = half; x < 128; x += 2) {
        unsigned long long a = 0ull, b = 0ull;
        #pragma unroll
        for (int q = 0; q < 4; q++) {
            ulonglong2 vr = Fr2[x * 4 + q];
            ulonglong2 vi = Fi2[x * 4 + q];
            a = fma2(vr.x, C [2 * q],     a);
            a = fma2(vr.y, C [2 * q + 1], a);
            b = fma2(vi.x, Sn[2 * q],     b);
            b = fma2(vi.y, Sn[2 * q + 1], b);
        }
        float A = f2lo(a) + f2hi(a);
        float B = f2lo(b) + f2hi(b);
        float* orow = obase + (size_t)x * (128 * NZ);
        __stcs(orow + zp, A - B);
        if (zp >= 1 && zp < 127) __stcs(orow + 254 - zp, A + B);
    }
}

// ---------------- launch ----------------
extern "C" void kernel_launch(void* const* d_in, const int* in_sizes, int n_in,
                              void* d_out, int out_size) {
    const float* Br  = (const float*)d_in[0];
    const float* Bp  = (const float*)d_in[1];
    const float* Bt  = (const float*)d_in[2];
    const float* W1  = (const float*)d_in[3];
    const float* b1  = (const float*)d_in[4];
    const float* W2r = (const float*)d_in[5];
    const float* W2i = (const float*)d_in[6];
    const float* b2r = (const float*)d_in[7];
    const float* b2i = (const float*)d_in[8];
    float* out = (float*)d_out;

    static int inited = 0;
    if (!inited) {
        cudaFuncSetAttribute(k_mlp2, cudaFuncAttributeMaxDynamicSharedMemorySize,
                             MLP2_SMEM);
        inited = 1;
    }

    // serial schedule: mlp2 runs as a pure-read phase (concurrency hurts TMA)
    k_init_tw<<<16, 256>>>();
    k_dft_y  <<<384, 128>>>(Br, Bp, Bt);
    k_dft_x  <<<96, 256>>>();
    k_mlp1   <<<512, 256>>>(W1, b1);
    k_mlp2   <<<MLP2_GRID, 256, MLP2_SMEM>>>(0, DOUT, W2r, W2i, b2r, b2i);
    k_stage_y<<<dim3(32, 3, 4), 256>>>();
    k_stage_xz<<<dim3(128, 12), 256>>>(out);
}

// round 15
// speedup vs baseline: 1.2987x; 1.2202x over previous
#include <cuda_runtime.h>
#include <math.h>
#include <stdint.h>

#define SS   16
#define NG   128
#define NZ   254          // output length along z = 2*(128-1)
#define DIN  3072
#define DH   1024
#define DOUT 49152
#define PI_D 3.14159265358979323846

#define MLP2_GRID   148
#define MLP2_SLOT   8192                      // one W2r row (4KB) + one W2i row (4KB)
#define MLP2_SMEM   (8 * 3 * MLP2_SLOT)       // 8 warps x 3-slot ring = 192 KB

// ---------------- scratch (device globals; no allocations) ----------------
__device__ __align__(16) float2 g_Cy[3 * 128 * 16];      // y-DFT of boundary fields
__device__ __align__(16) float  g_xr[DIN];               // MLP input (real)
__device__             float   g_h [DH];                 // hidden layer
__device__ __align__(16) float2 g_o [DOUT];              // complex GEMV output (12,16,16,16)
__device__ __align__(16) float  g_Y1r[12 * 32 * 128 * 16]; // y-transform, real plane
__device__ __align__(16) float  g_Y1i[12 * 32 * 128 * 16]; // y-transform, imag plane
__device__             float2  g_tw128[128];             // e^{+2πi t/128}
__device__ __align__(16) float2 g_twc[8 * 128];          // (w cos) pairs: [k][u] -> kz=2k,2k+1
__device__ __align__(16) float2 g_tws[8 * 128];          // (w sin) pairs

// ---------------- packed f32x2 helpers ----------------
__device__ __forceinline__ unsigned long long fma2(unsigned long long a,
                                                   unsigned long long b,
                                                   unsigned long long c) {
    unsigned long long d;
    asm("fma.rn.f32x2 %0, %1, %2, %3;" : "=l"(d) : "l"(a), "l"(b), "l"(c));
    return d;
}
__device__ __forceinline__ unsigned long long add2(unsigned long long a,
                                                   unsigned long long b) {
    unsigned long long d;
    asm("add.rn.f32x2 %0, %1, %2;" : "=l"(d) : "l"(a), "l"(b));
    return d;
}
__device__ __forceinline__ float f2lo(unsigned long long u) {
    return __uint_as_float((unsigned int)u);
}
__device__ __forceinline__ float f2hi(unsigned long long u) {
    return __uint_as_float((unsigned int)(u >> 32));
}
__device__ __forceinline__ unsigned long long pack2(float a, float b) {
    return (unsigned long long)__float_as_uint(a) |
           ((unsigned long long)__float_as_uint(b) << 32);
}

// ---------------- mbarrier / bulk-async helpers ----------------
__device__ __forceinline__ uint32_t smem_u32(const void* p) {
    uint32_t a;
    asm("{ .reg .u64 t; cvta.to.shared.u64 t, %1; cvt.u32.u64 %0, t; }"
        : "=r"(a) : "l"(p));
    return a;
}
__device__ __forceinline__ void mbar_init(uint32_t mbar, uint32_t count) {
    asm volatile("mbarrier.init.shared.b64 [%0], %1;" :: "r"(mbar), "r"(count)
                 : "memory");
}
__device__ __forceinline__ void mbar_expect_tx(uint32_t mbar, uint32_t bytes) {
    asm volatile("mbarrier.arrive.expect_tx.shared.b64 _, [%0], %1;"
                 :: "r"(mbar), "r"(bytes) : "memory");
}
__device__ __forceinline__ void mbar_wait(uint32_t mbar, uint32_t phase) {
    asm volatile(
        "{\n\t"
        ".reg .pred P1;\n\t"
        "WAIT_LOOP_%=:\n\t"
        "mbarrier.try_wait.parity.acquire.cta.shared::cta.b64 P1, [%0], %1, 0x989680;\n\t"
        "@P1 bra.uni WAIT_DONE_%=;\n\t"
        "bra.uni WAIT_LOOP_%=;\n\t"
        "WAIT_DONE_%=:\n\t"
        "}"
        :: "r"(mbar), "r"(phase) : "memory");
}
__device__ __forceinline__ void bulk_g2s(uint32_t dst, const void* src,
                                         uint32_t bytes, uint32_t mbar) {
    asm volatile(
        "cp.async.bulk.shared::cta.global.mbarrier::complete_tx::bytes "
        "[%0], [%1], %2, [%3];"
        :: "r"(dst), "l"(src), "r"(bytes), "r"(mbar) : "memory");
}
__device__ __forceinline__ void fence_proxy_async_shared() {
    asm volatile("fence.proxy.async.shared::cta;" ::: "memory");
}

// ---------------- K0: twiddle tables (double precision, deterministic) ----
__global__ void k_init_tw() {
    int i = blockIdx.x * blockDim.x + threadIdx.x;
    if (i < 128) {
        double a = 2.0 * PI_D * (double)i / 128.0;
        g_tw128[i] = make_float2((float)cos(a), (float)sin(a));
    }
    if (i < 8 * 128) {
        int k = i >> 7, zp = i & 127;
        double n3 = (double)NG * (double)NG * (double)NZ;
        int kz0 = 2 * k, kz1 = 2 * k + 1;
        double w0 = (kz0 == 0 ? 1.0 : 2.0) / n3;
        double w1 = 2.0 / n3;
        double a0 = 2.0 * PI_D * (double)(kz0 * zp) / (double)NZ;
        double a1 = 2.0 * PI_D * (double)(kz1 * zp) / (double)NZ;
        g_twc[i] = make_float2((float)(w0 * cos(a0)), (float)(w1 * cos(a1)));
        g_tws[i] = make_float2((float)(w0 * sin(a0)), (float)(w1 * sin(a1)));
    }
}

// ---------------- K1a: forward DFT along y (16 modes) ----------------
__global__ void k_dft_y(const float* __restrict__ Br, const float* __restrict__ Bp,
                        const float* __restrict__ Bt) {
    int f = blockIdx.x >> 7;
    int x = blockIdx.x & 127;
    const float* src = (f == 0) ? Bp : (f == 1) ? Bt : Br;
    float sgn = (f == 1) ? -1.f : 1.f;
    __shared__ float  row[128];
    __shared__ float2 tw[128];
    int t = threadIdx.x;
    row[t] = sgn * src[x * 128 + t];
    tw[t]  = g_tw128[t];
    __syncthreads();
    if (t < 16) {
        float re = 0.f, im = 0.f;
        #pragma unroll 8
        for (int y = 0; y < 128; y++) {
            float2 w = tw[(t * y) & 127];
            float v = row[y];
            re += v * w.x;
            im -= v * w.y;
        }
        g_Cy[(f * 128 + x) * 16 + t] = make_float2(re, im);
    }
}

// ---------------- K1b: forward DFT along x (32 modes) -> xr --------------
__global__ __launch_bounds__(256) void k_dft_x() {
    int b = blockIdx.x;           // 0..95  (f*32 + kxi)
    int f = b / 32, kxi = b % 32;
    __shared__ float2 tw[128];
    __shared__ float2 red[256];
    int t = threadIdx.x;
    if (t < 128) tw[t] = g_tw128[t];
    __syncthreads();
    int ky = t & 15, xc = t >> 4;           // xc: 0..15, 8 x's each
    int kxe = (kxi < 16) ? kxi : (kxi + 96);
    float re = 0.f, im = 0.f;
    #pragma unroll
    for (int j = 0; j < 8; j++) {
        int x = xc * 8 + j;
        float2 c = g_Cy[(f * 128 + x) * 16 + ky];
        float2 w = tw[(kxe * x) & 127];
        re += c.x * w.x + c.y * w.y;
        im += c.y * w.x - c.x * w.y;
    }
    red[t] = make_float2(re, im);
    __syncthreads();
    #pragma unroll
    for (int s = 8; s >= 1; s >>= 1) {
        if (xc < s) {
            red[t].x += red[t + 16 * s].x;
            red[t].y += red[t + 16 * s].y;
        }
        __syncthreads();
    }
    if (t < 16) {
        int seg = f * 512 + (kxi >= 16 ? 256 : 0) + (kxi & 15) * 16 + t;
        g_xr[seg]        = red[t].x;
        g_xr[1536 + seg] = red[t].y;
    }
}

// ---------------- K2: hidden GEMV + sigmoid (no staging, direct L2) ------
__global__ __launch_bounds__(256) void k_mlp1(const float* __restrict__ W1,
                                              const float* __restrict__ b1) {
    __shared__ float part[8];
    int t = threadIdx.x;
    int w = t >> 5, lane = t & 31;
    int row = blockIdx.x * 2 + (w >> 2);    // 2 rows per block
    int q   = w & 3;                        // quarter of the row
    const float4* wr = (const float4*)(W1 + (size_t)row * DIN) + q * 192;
    const float4* xv = ((const float4*)g_xr) + q * 192;
    float acc = 0.f;
    #pragma unroll
    for (int k = 0; k < 6; k++) {
        int j = lane + 32 * k;
        float4 a = wr[j];
        float4 x4 = __ldg(xv + j);
        acc += a.x * x4.x + a.y * x4.y + a.z * x4.z + a.w * x4.w;
    }
    #pragma unroll
    for (int o = 16; o > 0; o >>= 1)
        acc += __shfl_xor_sync(0xffffffffu, acc, o);
    if (lane == 0) part[w] = acc;
    __syncthreads();
    if (t < 2) {
        int r2 = blockIdx.x * 2 + t;
        float v = part[t * 4] + part[t * 4 + 1] + part[t * 4 + 2] + part[t * 4 + 3]
                + b1[r2];
        g_h[r2] = 1.f / (1.f + expf(-v));
    }
}

// ---------------- K3: complex GEMV — per-warp TMA ring, ONE launch -------
// 148 persistent CTAs x 8 warps, grid-strided over all rows. Runs serial,
// pure-read stream at ~5.3 TB/s (measured R13).
__global__ __launch_bounds__(256) void k_mlp2(int row0, int nrows,
                                              const float* __restrict__ W2r,
                                              const float* __restrict__ W2i,
                                              const float* __restrict__ b2r,
                                              const float* __restrict__ b2i) {
    extern __shared__ __align__(16) unsigned char sbuf[];   // 8*3*8192
    __shared__ __align__(16) float sh[DH];
    __shared__ __align__(8) unsigned long long mbars[24];
    int t = threadIdx.x;
    for (int i = t; i < DH; i += 256) sh[i] = g_h[i];
    if (t < 24) mbar_init(smem_u32(&mbars[t]), 1);
    fence_proxy_async_shared();
    __syncthreads();

    int w = t >> 5, lane = t & 31;
    const int stride = MLP2_GRID * 8;               // 1184 warps total
    int wg = blockIdx.x * 8 + w;
    int nIter = (nrows - wg + stride - 1) / stride;

    uint32_t slot0 = smem_u32(sbuf) + (uint32_t)(w * 3) * MLP2_SLOT;
    uint32_t mb0   = smem_u32(&mbars[w * 3]);

    // prologue: fill up to 3 slots
    if (lane == 0) {
        int pre = nIter < 3 ? nIter : 3;
        for (int s = 0; s < pre; s++) {
            size_t row = (size_t)row0 + wg + (size_t)s * stride;
            uint32_t mb = mb0 + s * 8;
            mbar_expect_tx(mb, MLP2_SLOT);
            bulk_g2s(slot0 + s * MLP2_SLOT,        W2r + row * DH, 4096, mb);
            bulk_g2s(slot0 + s * MLP2_SLOT + 4096, W2i + row * DH, 4096, mb);
        }
    }

    const float4* hv = (const float4*)sh;
    unsigned int phbits = 0;
    int s = 0;
    for (int i = 0; i < nIter; i++) {
        uint32_t mb = mb0 + s * 8;
        mbar_wait(mb, (phbits >> s) & 1u);
        phbits ^= 1u << s;

        const float4* r4 = (const float4*)(sbuf + (w * 3 + s) * MLP2_SLOT);
        const float4* i4 = r4 + 256;
        float ar = 0.f, ai = 0.f;
        #pragma unroll
        for (int k = 0; k < 8; k++) {
            int j = lane + 32 * k;
            float4 h4 = hv[j];
            float4 a = r4[j];
            float4 b = i4[j];
            ar += a.x * h4.x + a.y * h4.y + a.z * h4.z + a.w * h4.w;
            ai += b.x * h4.x + b.y * h4.y + b.z * h4.z + b.w * h4.w;
        }
        #pragma unroll
        for (int o = 16; o > 0; o >>= 1) {
            ar += __shfl_xor_sync(0xffffffffu, ar, o);
            ai += __shfl_xor_sync(0xffffffffu, ai, o);
        }
        int row = row0 + wg + i * stride;
        if (lane == 0) g_o[row] = make_float2(ar + b2r[row], ai + b2i[row]);

        __syncwarp();
        if (i + 3 < nIter && lane == 0) {      // refill this slot
            size_t nrow = (size_t)row + (size_t)3 * stride;
            mbar_expect_tx(mb, MLP2_SLOT);
            bulk_g2s(slot0 + s * MLP2_SLOT,        W2r + nrow * DH, 4096, mb);
            bulk_g2s(slot0 + s * MLP2_SLOT + 4096, W2i + nrow * DH, 4096, mb);
        }
        s = (s == 2) ? 0 : s + 1;
    }
}

// ---------------- K4: inverse DFT along y (all fields) -------------------
__global__ void k_stage_y() {
    int kxi = blockIdx.x;   // 0..31
    int f   = blockIdx.y;   // 0..2
    int yt  = blockIdx.z;   // 0..3
    __shared__ float2 Bsh[512];
    __shared__ float2 tw[128];
    int t = threadIdx.x;
    if (t < 128) tw[t] = g_tw128[t];
    int hx = (kxi >= 16) ? 1 : 0, p = kxi & 15;
    for (int e = t; e < 512; e += 256) {
        int kyi = e >> 4, kz = e & 15;
        int blk = f * 4 + hx * 2 + (kyi >= 16 ? 1 : 0);
        Bsh[e] = g_o[blk * 4096 + p * 256 + (kyi & 15) * 16 + kz];
    }
    __syncthreads();
    float mx = (kxi < 16) ? (float)kxi : (float)(kxi - 32);
    for (int it = t; it < 512; it += 256) {
        int y  = yt * 32 + (it >> 4);
        int kz = it & 15;
        float Sr = 0.f, Si = 0.f, Tr = 0.f, Ti = 0.f;
        #pragma unroll
        for (int kyi = 0; kyi < 32; kyi++) {
            int   kye = (kyi < 16) ? kyi : (kyi + 96);
            float my  = (kyi < 16) ? (float)kyi : (float)(kyi - 32);
            float2 w = tw[(kye * y) & 127];
            float2 B = Bsh[kyi * 16 + kz];
            Sr += B.x * w.x - B.y * w.y;
            Si += B.x * w.y + B.y * w.x;
            float br = -my * B.y, bi = my * B.x;   // i*my*B
            Tr += br * w.x - bi * w.y;
            Ti += br * w.y + bi * w.x;
        }
        int rest = (kxi * 128 + y) * 16 + kz;
        float fz = (float)kz;
        g_Y1r[ f          * 65536 + rest] = Sr;
        g_Y1i[ f          * 65536 + rest] = Si;
        g_Y1r[(3 + 3 * f) * 65536 + rest] = -mx * Si;
        g_Y1i[(3 + 3 * f) * 65536 + rest] =  mx * Sr;
        g_Y1r[(4 + 3 * f) * 65536 + rest] = Tr;
        g_Y1i[(4 + 3 * f) * 65536 + rest] = Ti;
        g_Y1r[(5 + 3 * f) * 65536 + rest] = -fz * Si;
        g_Y1i[(5 + 3 * f) * 65536 + rest] =  fz * Sr;
    }
}

// ---------------- K5: FUSED x-DFT + z-transform, double symmetry ---------
// Phase 1 (x-fold): w(kxe, x+64) = (-1)^kxi w(kxe, x). Accumulate even/odd
// kxi partials for x<64; F(x)=E+O, F(x+64)=E-O. Thread = (x<64, kz-quad).
// Phase 2 (z-quarter): packed (even,odd) kz lanes give Ae/Ao/Be/Bo from one
// 16-fma2 dot; combos yield z in {u, 127-u, 127+u, 254-u}.
__global__ __launch_bounds__(256) void k_stage_xz(float* __restrict__ out) {
    int y = blockIdx.x;                 // 0..127
    int c = blockIdx.y;                 // 0..11
    __shared__ __align__(16) float Yr[512];
    __shared__ __align__(16) float Yi[512];
    __shared__ __align__(16) float Frs[2048];   // [x][16 kz]
    __shared__ __align__(16) float Fis[2048];
    __shared__ float2 tw[128];
    int t = threadIdx.x;
    if (t < 128) tw[t] = g_tw128[t];
    for (int e = t; e < 512; e += 256) {
        int idx = c * 65536 + ((e >> 4) * 128 + y) * 16 + (e & 15);
        Yr[e] = g_Y1r[idx];
        Yi[e] = g_Y1i[idx];
    }
    __syncthreads();

    // ---- Phase 1: folded x-DFT ----
    {
        int xb  = t & 63;          // x base (0..63)
        int kzq = t >> 6;          // 0..3 -> kzp pair (2kzq, 2kzq+1) = kz 4kzq..4kzq+3
        const ulonglong2* Yr4 = (const ulonglong2*)Yr;  // [kxi*4 + kzq]
        const ulonglong2* Yi4 = (const ulonglong2*)Yi;
        unsigned long long reA[2][2] = {{0ull,0ull},{0ull,0ull}};  // [kzp_loc][parity]
        unsigned long long imA[2][2] = {{0ull,0ull},{0ull,0ull}};
        #pragma unroll
        for (int kxi = 0; kxi < 32; kxi++) {
            int kxe = (kxi < 16) ? kxi : (kxi + 96);
            const int p = kxi & 1;
            float2 w = tw[(kxe * xb) & 127];
            unsigned long long wx2 = pack2(w.x,  w.x);
            unsigned long long wy2 = pack2(w.y,  w.y);
            unsigned long long wyn = pack2(-w.y, -w.y);
            ulonglong2 vr = Yr4[kxi * 4 + kzq];
            ulonglong2 vi = Yi4[kxi * 4 + kzq];
            reA[0][p] = fma2(vr.x, wx2, reA[0][p]);
            reA[0][p] = fma2(vi.x, wyn, reA[0][p]);
            imA[0][p] = fma2(vr.x, wy2, imA[0][p]);
            imA[0][p] = fma2(vi.x, wx2, imA[0][p]);
            reA[1][p] = fma2(vr.y, wx2, reA[1][p]);
            reA[1][p] = fma2(vi.y, wyn, reA[1][p]);
            imA[1][p] = fma2(vr.y, wy2, imA[1][p]);
            imA[1][p] = fma2(vi.y, wx2, imA[1][p]);
        }
        unsigned long long neg1 = pack2(-1.f, -1.f);
        ulonglong2* FrW = (ulonglong2*)Frs;   // [x*4 + kzq]
        ulonglong2* FiW = (ulonglong2*)Fis;
        ulonglong2 rsum, isum, rdif, idif;
        rsum.x = add2(reA[0][0], reA[0][1]);  rsum.y = add2(reA[1][0], reA[1][1]);
        isum.x = add2(imA[0][0], imA[0][1]);  isum.y = add2(imA[1][0], imA[1][1]);
        rdif.x = fma2(reA[0][1], neg1, reA[0][0]);  rdif.y = fma2(reA[1][1], neg1, reA[1][0]);
        idif.x = fma2(imA[0][1], neg1, imA[0][0]);  idif.y = fma2(imA[1][1], neg1, imA[1][0]);
        FrW[xb * 4 + kzq] = rsum;          FiW[xb * 4 + kzq] = isum;
        FrW[(xb + 64) * 4 + kzq] = rdif;   FiW[(xb + 64) * 4 + kzq] = idif;
    }
    __syncthreads();

    // ---- Phase 2: z-transform, quarter-range u with two symmetries ----
    int u  = t & 63;        // 0..63
    int xq = t >> 6;        // 0..3, x stride 4
    unsigned long long C[8], Sn[8];
    #pragma unroll
    for (int k = 0; k < 8; k++) {
        float2 cc = g_twc[k * 128 + u];
        float2 ss = g_tws[k * 128 + u];
        C [k] = pack2(cc.x, cc.y);
        Sn[k] = pack2(ss.x, ss.y);
    }
    const ulonglong2* Fr2 = (const ulonglong2*)Frs;  // [x*4 + q]
    const ulonglong2* Fi2 = (const ulonglong2*)Fis;
    float* obase = out + ((size_t)c * 128 * 128 + y) * NZ;
    for (int x = xq; x < 128; x += 4) {
        unsigned long long a = 0ull, b = 0ull;
        #pragma unroll
        for (int q = 0; q < 4; q++) {
            ulonglong2 vr = Fr2[x * 4 + q];
            ulonglong2 vi = Fi2[x * 4 + q];
            a = fma2(vr.x, C [2 * q],     a);
            a = fma2(vr.y, C [2 * q + 1], a);
            b = fma2(vi.x, Sn[2 * q],     b);
            b = fma2(vi.y, Sn[2 * q + 1], b);
        }
        float Ae = f2lo(a), Ao = f2hi(a);
        float Be = f2lo(b), Bo = f2hi(b);
        float s1 = Ae + Ao, s2 = Be + Bo;
        float d1 = Ae - Ao, d2 = Be - Bo;
        float* orow = obase + (size_t)x * (128 * NZ);
        __stcs(orow + u,        s1 - s2);      // z = u
        __stcs(orow + 127 + u,  d1 - d2);      // z = 127+u
        if (u) {
            __stcs(orow + 254 - u, s1 + s2);   // z = 254-u
            __stcs(orow + 127 - u, d1 + d2);   // z = 127-u
        }
    }
}

// ---------------- launch ----------------
extern "C" void kernel_launch(void* const* d_in, const int* in_sizes, int n_in,
                              void* d_out, int out_size) {
    const float* Br  = (const float*)d_in[0];
    const float* Bp  = (const float*)d_in[1];
    const float* Bt  = (const float*)d_in[2];
    const float* W1  = (const float*)d_in[3];
    const float* b1  = (const float*)d_in[4];
    const float* W2r = (const float*)d_in[5];
    const float* W2i = (const float*)d_in[6];
    const float* b2r = (const float*)d_in[7];
    const float* b2i = (const float*)d_in[8];
    float* out = (float*)d_out;

    static int inited = 0;
    if (!inited) {
        cudaFuncSetAttribute(k_mlp2, cudaFuncAttributeMaxDynamicSharedMemorySize,
                             MLP2_SMEM);
        inited = 1;
    }

    // serial schedule: mlp2 runs as a pure-read phase (concurrency hurts TMA)
    k_init_tw<<<16, 256>>>();
    k_dft_y  <<<384, 128>>>(Br, Bp, Bt);
    k_dft_x  <<<96, 256>>>();
    k_mlp1   <<<512, 256>>>(W1, b1);
    k_mlp2   <<<MLP2_GRID, 256, MLP2_SMEM>>>(0, DOUT, W2r, W2i, b2r, b2i);
    k_stage_y<<<dim3(32, 3, 4), 256>>>();
    k_stage_xz<<<dim3(128, 12), 256>>>(out);
}

// round 16
// speedup vs baseline: 1.2995x; 1.0006x over previous
#include <cuda_runtime.h>
#include <math.h>
#include <stdint.h>

#define SS   16
#define NG   128
#define NZ   254          // output length along z = 2*(128-1)
#define DIN  3072
#define DH   1024
#define DOUT 49152
#define PI_D 3.14159265358979323846

#define MLP2_GRID   148
#define MLP2_SLOT   8192                      // one W2r row (4KB) + one W2i row (4KB)
#define MLP2_SMEM   (8 * 3 * MLP2_SLOT)       // 8 warps x 3-slot ring = 192 KB
#define MLP1_SMEM   (8 * DIN * 4)             // 8 rows x 12 KB = 96 KB

// ---------------- scratch (device globals; no allocations) ----------------
__device__ __align__(16) float2 g_Cy[3 * 128 * 16];      // y-DFT of boundary fields
__device__ __align__(16) float  g_xr[DIN];               // MLP input (real)
__device__             float   g_h [DH];                 // hidden layer
__device__ __align__(16) float2 g_o [DOUT];              // complex GEMV output (12,16,16,16)
__device__ __align__(16) float  g_Y1r[12 * 32 * 128 * 16]; // y-transform, real plane
__device__ __align__(16) float  g_Y1i[12 * 32 * 128 * 16]; // y-transform, imag plane
__device__             float2  g_tw128[128];             // e^{+2πi t/128}
__device__ __align__(16) float2 g_twc[8 * 128];          // (w cos) pairs: [k][u] -> kz=2k,2k+1
__device__ __align__(16) float2 g_tws[8 * 128];          // (w sin) pairs

// ---------------- packed f32x2 helpers ----------------
__device__ __forceinline__ unsigned long long fma2(unsigned long long a,
                                                   unsigned long long b,
                                                   unsigned long long c) {
    unsigned long long d;
    asm("fma.rn.f32x2 %0, %1, %2, %3;" : "=l"(d) : "l"(a), "l"(b), "l"(c));
    return d;
}
__device__ __forceinline__ unsigned long long add2(unsigned long long a,
                                                   unsigned long long b) {
    unsigned long long d;
    asm("add.rn.f32x2 %0, %1, %2;" : "=l"(d) : "l"(a), "l"(b));
    return d;
}
__device__ __forceinline__ float f2lo(unsigned long long u) {
    return __uint_as_float((unsigned int)u);
}
__device__ __forceinline__ float f2hi(unsigned long long u) {
    return __uint_as_float((unsigned int)(u >> 32));
}
__device__ __forceinline__ unsigned long long pack2(float a, float b) {
    return (unsigned long long)__float_as_uint(a) |
           ((unsigned long long)__float_as_uint(b) << 32);
}

// ---------------- mbarrier / bulk-async helpers ----------------
__device__ __forceinline__ uint32_t smem_u32(const void* p) {
    uint32_t a;
    asm("{ .reg .u64 t; cvta.to.shared.u64 t, %1; cvt.u32.u64 %0, t; }"
        : "=r"(a) : "l"(p));
    return a;
}
__device__ __forceinline__ void mbar_init(uint32_t mbar, uint32_t count) {
    asm volatile("mbarrier.init.shared.b64 [%0], %1;" :: "r"(mbar), "r"(count)
                 : "memory");
}
__device__ __forceinline__ void mbar_expect_tx(uint32_t mbar, uint32_t bytes) {
    asm volatile("mbarrier.arrive.expect_tx.shared.b64 _, [%0], %1;"
                 :: "r"(mbar), "r"(bytes) : "memory");
}
__device__ __forceinline__ void mbar_wait(uint32_t mbar, uint32_t phase) {
    asm volatile(
        "{\n\t"
        ".reg .pred P1;\n\t"
        "WAIT_LOOP_%=:\n\t"
        "mbarrier.try_wait.parity.acquire.cta.shared::cta.b64 P1, [%0], %1, 0x989680;\n\t"
        "@P1 bra.uni WAIT_DONE_%=;\n\t"
        "bra.uni WAIT_LOOP_%=;\n\t"
        "WAIT_DONE_%=:\n\t"
        "}"
        :: "r"(mbar), "r"(phase) : "memory");
}
__device__ __forceinline__ void bulk_g2s(uint32_t dst, const void* src,
                                         uint32_t bytes, uint32_t mbar) {
    asm volatile(
        "cp.async.bulk.shared::cta.global.mbarrier::complete_tx::bytes "
        "[%0], [%1], %2, [%3];"
        :: "r"(dst), "l"(src), "r"(bytes), "r"(mbar) : "memory");
}
__device__ __forceinline__ void fence_proxy_async_shared() {
    asm volatile("fence.proxy.async.shared::cta;" ::: "memory");
}

// ---------------- K0: twiddle tables (double precision, deterministic) ----
__global__ void k_init_tw() {
    int i = blockIdx.x * blockDim.x + threadIdx.x;
    if (i < 128) {
        double a = 2.0 * PI_D * (double)i / 128.0;
        g_tw128[i] = make_float2((float)cos(a), (float)sin(a));
    }
    if (i < 8 * 128) {
        int k = i >> 7, zp = i & 127;
        double n3 = (double)NG * (double)NG * (double)NZ;
        int kz0 = 2 * k, kz1 = 2 * k + 1;
        double w0 = (kz0 == 0 ? 1.0 : 2.0) / n3;
        double w1 = 2.0 / n3;
        double a0 = 2.0 * PI_D * (double)(kz0 * zp) / (double)NZ;
        double a1 = 2.0 * PI_D * (double)(kz1 * zp) / (double)NZ;
        g_twc[i] = make_float2((float)(w0 * cos(a0)), (float)(w1 * cos(a1)));
        g_tws[i] = make_float2((float)(w0 * sin(a0)), (float)(w1 * sin(a1)));
    }
}

// ---------------- K1a: forward DFT along y (16 modes) ----------------
__global__ void k_dft_y(const float* __restrict__ Br, const float* __restrict__ Bp,
                        const float* __restrict__ Bt) {
    int f = blockIdx.x >> 7;
    int x = blockIdx.x & 127;
    const float* src = (f == 0) ? Bp : (f == 1) ? Bt : Br;
    float sgn = (f == 1) ? -1.f : 1.f;
    __shared__ float  row[128];
    __shared__ float2 tw[128];
    int t = threadIdx.x;
    row[t] = sgn * src[x * 128 + t];
    tw[t]  = g_tw128[t];
    __syncthreads();
    if (t < 16) {
        float re = 0.f, im = 0.f;
        #pragma unroll 8
        for (int y = 0; y < 128; y++) {
            float2 w = tw[(t * y) & 127];
            float v = row[y];
            re += v * w.x;
            im -= v * w.y;
        }
        g_Cy[(f * 128 + x) * 16 + t] = make_float2(re, im);
    }
}

// ---------------- K1b: forward DFT along x (32 modes) -> xr --------------
__global__ __launch_bounds__(256) void k_dft_x() {
    int b = blockIdx.x;           // 0..95  (f*32 + kxi)
    int f = b / 32, kxi = b % 32;
    __shared__ float2 tw[128];
    __shared__ float2 red[256];
    int t = threadIdx.x;
    if (t < 128) tw[t] = g_tw128[t];
    __syncthreads();
    int ky = t & 15, xc = t >> 4;           // xc: 0..15, 8 x's each
    int kxe = (kxi < 16) ? kxi : (kxi + 96);
    float re = 0.f, im = 0.f;
    #pragma unroll
    for (int j = 0; j < 8; j++) {
        int x = xc * 8 + j;
        float2 c = g_Cy[(f * 128 + x) * 16 + ky];
        float2 w = tw[(kxe * x) & 127];
        re += c.x * w.x + c.y * w.y;
        im += c.y * w.x - c.x * w.y;
    }
    red[t] = make_float2(re, im);
    __syncthreads();
    #pragma unroll
    for (int s = 8; s >= 1; s >>= 1) {
        if (xc < s) {
            red[t].x += red[t + 16 * s].x;
            red[t].y += red[t + 16 * s].y;
        }
        __syncthreads();
    }
    if (t < 16) {
        int seg = f * 512 + (kxi >= 16 ? 256 : 0) + (kxi & 15) * 16 + t;
        g_xr[seg]        = red[t].x;
        g_xr[1536 + seg] = red[t].y;
    }
}

// ---------------- K2: hidden GEMV + sigmoid — TMA per-warp row fetch -----
// 128 CTAs x 8 warps = 1024 warps, one row each. One cp.async.bulk brings
// the whole 12 KB row into smem; x-vector comes from L2 via __ldg.
__global__ __launch_bounds__(256) void k_mlp1(const float* __restrict__ W1,
                                              const float* __restrict__ b1) {
    extern __shared__ __align__(16) unsigned char m1buf[];   // 8 x 12 KB
    __shared__ __align__(8) unsigned long long mbars1[8];
    int t = threadIdx.x;
    int w = t >> 5, lane = t & 31;
    if (t < 8) mbar_init(smem_u32(&mbars1[t]), 1);
    fence_proxy_async_shared();
    __syncthreads();

    int row = blockIdx.x * 8 + w;
    uint32_t slot = smem_u32(m1buf) + (uint32_t)w * (DIN * 4);
    uint32_t mb   = smem_u32(&mbars1[w]);
    if (lane == 0) {
        mbar_expect_tx(mb, DIN * 4);
        bulk_g2s(slot, W1 + (size_t)row * DIN, DIN * 4, mb);
    }
    mbar_wait(mb, 0);

    const float4* wr = (const float4*)(m1buf + (size_t)w * (DIN * 4));
    const float4* xv = (const float4*)g_xr;
    float acc = 0.f;
    #pragma unroll
    for (int k = 0; k < 24; k++) {
        int j = lane + 32 * k;
        float4 a = wr[j];
        float4 x4 = __ldg(xv + j);
        acc += a.x * x4.x + a.y * x4.y + a.z * x4.z + a.w * x4.w;
    }
    #pragma unroll
    for (int o = 16; o > 0; o >>= 1)
        acc += __shfl_xor_sync(0xffffffffu, acc, o);
    if (lane == 0) {
        float v = acc + b1[row];
        g_h[row] = 1.f / (1.f + expf(-v));
    }
}

// ---------------- K3: complex GEMV — per-warp TMA ring, ONE launch -------
// 148 persistent CTAs x 8 warps, grid-strided over all rows. Runs serial,
// pure-read stream at ~5.3 TB/s (measured R13).
__global__ __launch_bounds__(256) void k_mlp2(int row0, int nrows,
                                              const float* __restrict__ W2r,
                                              const float* __restrict__ W2i,
                                              const float* __restrict__ b2r,
                                              const float* __restrict__ b2i) {
    extern __shared__ __align__(16) unsigned char sbuf[];   // 8*3*8192
    __shared__ __align__(16) float sh[DH];
    __shared__ __align__(8) unsigned long long mbars[24];
    int t = threadIdx.x;
    for (int i = t; i < DH; i += 256) sh[i] = g_h[i];
    if (t < 24) mbar_init(smem_u32(&mbars[t]), 1);
    fence_proxy_async_shared();
    __syncthreads();

    int w = t >> 5, lane = t & 31;
    const int stride = MLP2_GRID * 8;               // 1184 warps total
    int wg = blockIdx.x * 8 + w;
    int nIter = (nrows - wg + stride - 1) / stride;

    uint32_t slot0 = smem_u32(sbuf) + (uint32_t)(w * 3) * MLP2_SLOT;
    uint32_t mb0   = smem_u32(&mbars[w * 3]);

    // prologue: fill up to 3 slots
    if (lane == 0) {
        int pre = nIter < 3 ? nIter : 3;
        for (int s = 0; s < pre; s++) {
            size_t row = (size_t)row0 + wg + (size_t)s * stride;
            uint32_t mb = mb0 + s * 8;
            mbar_expect_tx(mb, MLP2_SLOT);
            bulk_g2s(slot0 + s * MLP2_SLOT,        W2r + row * DH, 4096, mb);
            bulk_g2s(slot0 + s * MLP2_SLOT + 4096, W2i + row * DH, 4096, mb);
        }
    }

    const float4* hv = (const float4*)sh;
    unsigned int phbits = 0;
    int s = 0;
    for (int i = 0; i < nIter; i++) {
        uint32_t mb = mb0 + s * 8;
        mbar_wait(mb, (phbits >> s) & 1u);
        phbits ^= 1u << s;

        const float4* r4 = (const float4*)(sbuf + (w * 3 + s) * MLP2_SLOT);
        const float4* i4 = r4 + 256;
        float ar = 0.f, ai = 0.f;
        #pragma unroll
        for (int k = 0; k < 8; k++) {
            int j = lane + 32 * k;
            float4 h4 = hv[j];
            float4 a = r4[j];
            float4 b = i4[j];
            ar += a.x * h4.x + a.y * h4.y + a.z * h4.z + a.w * h4.w;
            ai += b.x * h4.x + b.y * h4.y + b.z * h4.z + b.w * h4.w;
        }
        #pragma unroll
        for (int o = 16; o > 0; o >>= 1) {
            ar += __shfl_xor_sync(0xffffffffu, ar, o);
            ai += __shfl_xor_sync(0xffffffffu, ai, o);
        }
        int row = row0 + wg + i * stride;
        if (lane == 0) g_o[row] = make_float2(ar + b2r[row], ai + b2i[row]);

        __syncwarp();
        if (i + 3 < nIter && lane == 0) {      // refill this slot
            size_t nrow = (size_t)row + (size_t)3 * stride;
            mbar_expect_tx(mb, MLP2_SLOT);
            bulk_g2s(slot0 + s * MLP2_SLOT,        W2r + nrow * DH, 4096, mb);
            bulk_g2s(slot0 + s * MLP2_SLOT + 4096, W2i + nrow * DH, 4096, mb);
        }
        s = (s == 2) ? 0 : s + 1;
    }
}

// ---------------- K4: inverse DFT along y (all fields) -------------------
__global__ void k_stage_y() {
    int kxi = blockIdx.x;   // 0..31
    int f   = blockIdx.y;   // 0..2
    int yt  = blockIdx.z;   // 0..3
    __shared__ float2 Bsh[512];
    __shared__ float2 tw[128];
    int t = threadIdx.x;
    if (t < 128) tw[t] = g_tw128[t];
    int hx = (kxi >= 16) ? 1 : 0, p = kxi & 15;
    for (int e = t; e < 512; e += 256) {
        int kyi = e >> 4, kz = e & 15;
        int blk = f * 4 + hx * 2 + (kyi >= 16 ? 1 : 0);
        Bsh[e] = g_o[blk * 4096 + p * 256 + (kyi & 15) * 16 + kz];
    }
    __syncthreads();
    float mx = (kxi < 16) ? (float)kxi : (float)(kxi - 32);
    for (int it = t; it < 512; it += 256) {
        int y  = yt * 32 + (it >> 4);
        int kz = it & 15;
        float Sr = 0.f, Si = 0.f, Tr = 0.f, Ti = 0.f;
        #pragma unroll
        for (int kyi = 0; kyi < 32; kyi++) {
            int   kye = (kyi < 16) ? kyi : (kyi + 96);
            float my  = (kyi < 16) ? (float)kyi : (float)(kyi - 32);
            float2 w = tw[(kye * y) & 127];
            float2 B = Bsh[kyi * 16 + kz];
            Sr += B.x * w.x - B.y * w.y;
            Si += B.x * w.y + B.y * w.x;
            float br = -my * B.y, bi = my * B.x;   // i*my*B
            Tr += br * w.x - bi * w.y;
            Ti += br * w.y + bi * w.x;
        }
        int rest = (kxi * 128 + y) * 16 + kz;
        float fz = (float)kz;
        g_Y1r[ f          * 65536 + rest] = Sr;
        g_Y1i[ f          * 65536 + rest] = Si;
        g_Y1r[(3 + 3 * f) * 65536 + rest] = -mx * Si;
        g_Y1i[(3 + 3 * f) * 65536 + rest] =  mx * Sr;
        g_Y1r[(4 + 3 * f) * 65536 + rest] = Tr;
        g_Y1i[(4 + 3 * f) * 65536 + rest] = Ti;
        g_Y1r[(5 + 3 * f) * 65536 + rest] = -fz * Si;
        g_Y1i[(5 + 3 * f) * 65536 + rest] =  fz * Sr;
    }
}

// ---------------- K5: FUSED x-DFT + z-transform, double symmetry ---------
// Phase 1 (x-fold): w(kxe, x+64) = (-1)^kxi w(kxe, x). Accumulate even/odd
// kxi partials for x<64; F(x)=E+O, F(x+64)=E-O. Thread = (x<64, kz-quad).
// Phase 2 (z-quarter): packed (even,odd) kz lanes give Ae/Ao/Be/Bo from one
// 16-fma2 dot; combos yield z in {u, 127-u, 127+u, 254-u}. 2 x per iter
// for 4 independent fma2 chains.
__global__ __launch_bounds__(256) void k_stage_xz(float* __restrict__ out) {
    int y = blockIdx.x;                 // 0..127
    int c = blockIdx.y;                 // 0..11
    __shared__ __align__(16) float Yr[512];
    __shared__ __align__(16) float Yi[512];
    __shared__ __align__(16) float Frs[2048];   // [x][16 kz]
    __shared__ __align__(16) float Fis[2048];
    __shared__ float2 tw[128];
    int t = threadIdx.x;
    if (t < 128) tw[t] = g_tw128[t];
    for (int e = t; e < 512; e += 256) {
        int idx = c * 65536 + ((e >> 4) * 128 + y) * 16 + (e & 15);
        Yr[e] = g_Y1r[idx];
        Yi[e] = g_Y1i[idx];
    }
    __syncthreads();

    // ---- Phase 1: folded x-DFT ----
    {
        int xb  = t & 63;          // x base (0..63)
        int kzq = t >> 6;          // 0..3 -> kzp pair (2kzq, 2kzq+1) = kz 4kzq..4kzq+3
        const ulonglong2* Yr4 = (const ulonglong2*)Yr;  // [kxi*4 + kzq]
        const ulonglong2* Yi4 = (const ulonglong2*)Yi;
        unsigned long long reA[2][2] = {{0ull,0ull},{0ull,0ull}};  // [kzp_loc][parity]
        unsigned long long imA[2][2] = {{0ull,0ull},{0ull,0ull}};
        #pragma unroll
        for (int kxi = 0; kxi < 32; kxi++) {
            int kxe = (kxi < 16) ? kxi : (kxi + 96);
            const int p = kxi & 1;
            float2 w = tw[(kxe * xb) & 127];
            unsigned long long wx2 = pack2(w.x,  w.x);
            unsigned long long wy2 = pack2(w.y,  w.y);
            unsigned long long wyn = pack2(-w.y, -w.y);
            ulonglong2 vr = Yr4[kxi * 4 + kzq];
            ulonglong2 vi = Yi4[kxi * 4 + kzq];
            reA[0][p] = fma2(vr.x, wx2, reA[0][p]);
            reA[0][p] = fma2(vi.x, wyn, reA[0][p]);
            imA[0][p] = fma2(vr.x, wy2, imA[0][p]);
            imA[0][p] = fma2(vi.x, wx2, imA[0][p]);
            reA[1][p] = fma2(vr.y, wx2, reA[1][p]);
            reA[1][p] = fma2(vi.y, wyn, reA[1][p]);
            imA[1][p] = fma2(vr.y, wy2, imA[1][p]);
            imA[1][p] = fma2(vi.y, wx2, imA[1][p]);
        }
        unsigned long long neg1 = pack2(-1.f, -1.f);
        ulonglong2* FrW = (ulonglong2*)Frs;   // [x*4 + kzq]
        ulonglong2* FiW = (ulonglong2*)Fis;
        ulonglong2 rsum, isum, rdif, idif;
        rsum.x = add2(reA[0][0], reA[0][1]);  rsum.y = add2(reA[1][0], reA[1][1]);
        isum.x = add2(imA[0][0], imA[0][1]);  isum.y = add2(imA[1][0], imA[1][1]);
        rdif.x = fma2(reA[0][1], neg1, reA[0][0]);  rdif.y = fma2(reA[1][1], neg1, reA[1][0]);
        idif.x = fma2(imA[0][1], neg1, imA[0][0]);  idif.y = fma2(imA[1][1], neg1, imA[1][0]);
        FrW[xb * 4 + kzq] = rsum;          FiW[xb * 4 + kzq] = isum;
        FrW[(xb + 64) * 4 + kzq] = rdif;   FiW[(xb + 64) * 4 + kzq] = idif;
    }
    __syncthreads();

    // ---- Phase 2: z-transform, quarter-range u, 2 x per iteration ----
    int u  = t & 63;        // 0..63
    int xq = t >> 6;        // 0..3
    unsigned long long C[8], Sn[8];
    #pragma unroll
    for (int k = 0; k < 8; k++) {
        float2 cc = g_twc[k * 128 + u];
        float2 ss = g_tws[k * 128 + u];
        C [k] = pack2(cc.x, cc.y);
        Sn[k] = pack2(ss.x, ss.y);
    }
    const ulonglong2* Fr2 = (const ulonglong2*)Frs;  // [x*4 + q]
    const ulonglong2* Fi2 = (const ulonglong2*)Fis;
    float* obase = out + ((size_t)c * 128 * 128 + y) * NZ;
    for (int x = xq; x < 128; x += 8) {
        int x1 = x + 4;
        unsigned long long a0 = 0ull, b0 = 0ull, a1 = 0ull, b1 = 0ull;
        #pragma unroll
        for (int q = 0; q < 4; q++) {
            ulonglong2 vr0 = Fr2[x  * 4 + q];
            ulonglong2 vi0 = Fi2[x  * 4 + q];
            ulonglong2 vr1 = Fr2[x1 * 4 + q];
            ulonglong2 vi1 = Fi2[x1 * 4 + q];
            a0 = fma2(vr0.x, C [2 * q],     a0);
            a1 = fma2(vr1.x, C [2 * q],     a1);
            b0 = fma2(vi0.x, Sn[2 * q],     b0);
            b1 = fma2(vi1.x, Sn[2 * q],     b1);
            a0 = fma2(vr0.y, C [2 * q + 1], a0);
            a1 = fma2(vr1.y, C [2 * q + 1], a1);
            b0 = fma2(vi0.y, Sn[2 * q + 1], b0);
            b1 = fma2(vi1.y, Sn[2 * q + 1], b1);
        }
        {
            float Ae = f2lo(a0), Ao = f2hi(a0);
            float Be = f2lo(b0), Bo = f2hi(b0);
            float s1 = Ae + Ao, s2 = Be + Bo;
            float d1 = Ae - Ao, d2 = Be - Bo;
            float* orow = obase + (size_t)x * (128 * NZ);
            __stcs(orow + u,        s1 - s2);      // z = u
            __stcs(orow + 127 + u,  d1 - d2);      // z = 127+u
            if (u) {
                __stcs(orow + 254 - u, s1 + s2);   // z = 254-u
                __stcs(orow + 127 - u, d1 + d2);   // z = 127-u
            }
        }
        {
            float Ae = f2lo(a1), Ao = f2hi(a1);
            float Be = f2lo(b1), Bo = f2hi(b1);
            float s1 = Ae + Ao, s2 = Be + Bo;
            float d1 = Ae - Ao, d2 = Be - Bo;
            float* orow = obase + (size_t)x1 * (128 * NZ);
            __stcs(orow + u,        s1 - s2);
            __stcs(orow + 127 + u,  d1 - d2);
            if (u) {
                __stcs(orow + 254 - u, s1 + s2);
                __stcs(orow + 127 - u, d1 + d2);
            }
        }
    }
}

// ---------------- launch ----------------
extern "C" void kernel_launch(void* const* d_in, const int* in_sizes, int n_in,
                              void* d_out, int out_size) {
    const float* Br  = (const float*)d_in[0];
    const float* Bp  = (const float*)d_in[1];
    const float* Bt  = (const float*)d_in[2];
    const float* W1  = (const float*)d_in[3];
    const float* b1  = (const float*)d_in[4];
    const float* W2r = (const float*)d_in[5];
    const float* W2i = (const float*)d_in[6];
    const float* b2r = (const float*)d_in[7];
    const float* b2i = (const float*)d_in[8];
    float* out = (float*)d_out;

    static int inited = 0;
    if (!inited) {
        cudaFuncSetAttribute(k_mlp2, cudaFuncAttributeMaxDynamicSharedMemorySize,
                             MLP2_SMEM);
        cudaFuncSetAttribute(k_mlp1, cudaFuncAttributeMaxDynamicSharedMemorySize,
                             MLP1_SMEM);
        inited = 1;
    }

    // serial schedule: mlp2 runs as a pure-read phase (concurrency hurts TMA)
    k_init_tw<<<16, 256>>>();
    k_dft_y  <<<384, 128>>>(Br, Bp, Bt);
    k_dft_x  <<<96, 256>>>();
    k_mlp1   <<<128, 256, MLP1_SMEM>>>(W1, b1);
    k_mlp2   <<<MLP2_GRID, 256, MLP2_SMEM>>>(0, DOUT, W2r, W2i, b2r, b2i);
    k_stage_y<<<dim3(32, 3, 4), 256>>>();
    k_stage_xz<<<dim3(128, 12), 256>>>(out);
}